// round 9
// baseline (speedup 1.0000x reference)
#include <cuda_runtime.h>
#include <cuda_bf16.h>
#include <math.h>
#include <string.h>

typedef unsigned int u32;
typedef unsigned long long u64;

// ---------------------------------------------------------------------------
// Problem constants
// ---------------------------------------------------------------------------
constexpr int T    = 64;
constexpr int B    = 2048;
constexpr int H    = 256;
constexpr int H1   = 64;
constexpr int H2   = 64;
constexpr int OUTD = 601;
constexpr int RROWS = 64;
constexpr int NTILE = T * B / RROWS;   // 2048 MLP tiles

// ---------------------------------------------------------------------------
// PTX helpers
// ---------------------------------------------------------------------------
__device__ __forceinline__ u32 smem_u32(const void* p) {
    u32 a;
    asm("{ .reg .u64 t; cvta.to.shared.u64 t, %1; cvt.u32.u64 %0, t; }"
        : "=r"(a) : "l"(p));
    return a;
}
__device__ __forceinline__ void ldsm_x4(u32& r0, u32& r1, u32& r2, u32& r3, u32 addr) {
    asm volatile("ldmatrix.sync.aligned.m8n8.x4.shared.b16 {%0,%1,%2,%3}, [%4];"
                 : "=r"(r0), "=r"(r1), "=r"(r2), "=r"(r3) : "r"(addr));
}
__device__ __forceinline__ void mma_bf16(float* d, const u32* a, const u32* b) {
    asm volatile(
        "mma.sync.aligned.m16n8k16.row.col.f32.bf16.bf16.f32 "
        "{%0,%1,%2,%3}, {%4,%5,%6,%7}, {%8,%9}, {%0,%1,%2,%3};"
        : "+f"(d[0]), "+f"(d[1]), "+f"(d[2]), "+f"(d[3])
        : "r"(a[0]), "r"(a[1]), "r"(a[2]), "r"(a[3]), "r"(b[0]), "r"(b[1]));
}
__device__ __forceinline__ void cp16(u32 dst, const void* src) {
    asm volatile("cp.async.ca.shared.global [%0], [%1], 16;" :: "r"(dst), "l"(src));
}
__device__ __forceinline__ void cp_commit() {
    asm volatile("cp.async.commit_group;" ::: "memory");
}
template <int N>
__device__ __forceinline__ void cp_wait_group() {
    asm volatile("cp.async.wait_group %0;" :: "n"(N) : "memory");
}
__device__ __forceinline__ void cp_wait_all() {
    asm volatile("cp.async.wait_all;" ::: "memory");
}
__device__ __forceinline__ u32 bf2u(__nv_bfloat162 v) {
    u32 r; memcpy(&r, &v, 4); return r;
}
__device__ __forceinline__ float2 u2f2(u32 v) {
    __nv_bfloat162 b; memcpy(&b, &v, 4);
    return make_float2(__bfloat162float(b.x), __bfloat162float(b.y));
}
__device__ __forceinline__ u64 ffma2(u64 a, u64 b, u64 c) {
    u64 d; asm("fma.rn.f32x2 %0, %1, %2, %3;" : "=l"(d) : "l"(a), "l"(b), "l"(c));
    return d;
}
__device__ __forceinline__ u64 pack2(float x, float y) {
    u64 d; asm("mov.b64 %0, {%1, %2};" : "=l"(d) : "f"(x), "f"(y));
    return d;
}
__device__ __forceinline__ float2 unpack2(u64 v) {
    float2 r; asm("mov.b64 {%0, %1}, %2;" : "=f"(r.x), "=f"(r.y) : "l"(v));
    return r;
}
constexpr float LOG2E = 1.4426950408889634f;
__device__ __forceinline__ float fast_sigmoid(float v) {
    float e; asm("ex2.approx.f32 %0, %1;" : "=f"(e) : "f"(-LOG2E * v));
    float r; asm("rcp.approx.f32 %0, %1;" : "=f"(r) : "f"(1.f + e));
    return r;
}
__device__ __forceinline__ float fast_tanh(float v) {
    float e; asm("ex2.approx.f32 %0, %1;" : "=f"(e) : "f"(2.f * LOG2E * v));
    float r; asm("rcp.approx.f32 %0, %1;" : "=f"(r) : "f"(1.f + e));
    return 1.f - 2.f * r;
}
__device__ __forceinline__ float fast_elu(float v) {
    if (v > 0.f) return v;
    float e; asm("ex2.approx.f32 %0, %1;" : "=f"(e) : "f"(LOG2E * v));
    return e - 1.f;
}

// ---------------------------------------------------------------------------
// Device scratch: h stored ONLY as t-indexed bf16 hi/lo (exact to ~2^-17)
// ---------------------------------------------------------------------------
__device__ u32 g_hhi[(size_t)T * B * (H / 2)];   // [t][b][kp] bf16x2 hi
__device__ u32 g_hlo[(size_t)T * B * (H / 2)];   // [t][b][kp] bf16x2 lo
__device__ __nv_bfloat16 g_whi[(size_t)3 * H * H];
__device__ __nv_bfloat16 g_wlo[(size_t)3 * H * H];
__device__ u32 g_cnt[32 * 32];    // per-bg monotonic arrival counters (128B apart)
__device__ u32 g_q;               // MLP tile queue

__global__ void prep_w_kernel(const float* __restrict__ w_hh)
{
    int i = blockIdx.x * blockDim.x + threadIdx.x;
    if (i < 3 * H * H) {
        float w = w_hh[i];
        __nv_bfloat16 hi = __float2bfloat16(w);
        g_whi[i] = hi;
        g_wlo[i] = __float2bfloat16(w - __bfloat162float(hi));
    }
    if (blockIdx.x == 0 && threadIdx.x < 32) {
        g_cnt[threadIdx.x * 32] = 0;
        if (threadIdx.x == 0) g_q = 0;
    }
}

// ---------------------------------------------------------------------------
// Fused persistent kernel: 148 blocks x 512 threads.
// Blocks 0..127: GRU producer (4 j-chunks x 32 batch-groups), then join MLP.
// Blocks 128..147: MLP consumers (tile queue, gated on g_cnt).
// ---------------------------------------------------------------------------
constexpr int GRID_P = 148;
constexpr int NGRU   = 128;
constexpr int SM_W      = 0;        // whi [4][192][128B]=98304 ; wlo at +98304
constexpr int SM_WLO_O  = 98304;
constexpr int SM_A      = 196608;   // 2 bufs x (hi 8192 + lo 8192)
constexpr int SM_PRM    = 229376;   // 7*64 f32 = 1792B
constexpr int SM_Q      = 231168;   // queue broadcast slot
constexpr int FUSED_SMEM = 231296;

struct AccT { float a[3][2][4]; };

__device__ __forceinline__ void mma_section(AccT& A, u32 ab, u32 wb,
                                            int wm, int wn,
                                            int a_row, int a_colh,
                                            int b_row, int b_colh)
{
    #pragma unroll
    for (int ks = 0; ks < 4; ks++) {
        u32 ahi[4], alo[4];
        {
            int r = wm * 16 + a_row;
            u32 off = (u32)(r * 128) + (u32)((ks * 32 + a_colh) ^ ((r & 7) << 4));
            ldsm_x4(ahi[0], ahi[1], ahi[2], ahi[3], ab + off);
            ldsm_x4(alo[0], alo[1], alo[2], alo[3], ab + 8192 + off);
        }
        #pragma unroll
        for (int g = 0; g < 3; g++) {
            int rr = g * 64 + wn * 16 + b_row;
            u32 off = (u32)(rr * 128) + (u32)((ks * 32 + b_colh) ^ ((rr & 7) << 4));
            u32 bh[4], bl[4];
            ldsm_x4(bh[0], bh[1], bh[2], bh[3], wb + off);
            ldsm_x4(bl[0], bl[1], bl[2], bl[3], wb + SM_WLO_O + off);
            mma_bf16(A.a[g][0], ahi, bh);
            mma_bf16(A.a[g][1], ahi, bh + 2);
            mma_bf16(A.a[g][0], ahi, bl);
            mma_bf16(A.a[g][1], ahi, bl + 2);
            mma_bf16(A.a[g][0], alo, bh);
            mma_bf16(A.a[g][1], alo, bh + 2);
        }
    }
}

__global__ void __launch_bounds__(512, 1)
fused_persist(const float* __restrict__ h0,
              const float* __restrict__ x,
              const float* __restrict__ w_ih,
              const float* __restrict__ b_ih,
              const float* __restrict__ b_hh,
              const float* __restrict__ w1, const float* __restrict__ b1,
              const float* __restrict__ w2, const float* __restrict__ b2,
              const float* __restrict__ w3, const float* __restrict__ b3,
              float* __restrict__ out)
{
    extern __shared__ char smem[];
    const u32 sb = smem_u32(smem);
    const int tid  = threadIdx.x;

    // =====================================================================
    // GRU producer part
    // =====================================================================
    if (blockIdx.x < NGRU) {
        float* sparam = (float*)(smem + SM_PRM);
        const int wid  = tid >> 5;
        const int lane = tid & 31;
        const int jc = blockIdx.x & 3;
        const int bg = blockIdx.x >> 2;
        const int j0 = jc * 64;
        const int b0 = bg * 64;
        const int wm = wid >> 2;
        const int wn = wid & 3;

        if (tid < 64) {
            int jg = j0 + tid;
            sparam[tid]        = w_ih[jg];
            sparam[64 + tid]   = w_ih[H + jg];
            sparam[128 + tid]  = w_ih[2 * H + jg];
            sparam[192 + tid]  = b_ih[jg]         + b_hh[jg];
            sparam[256 + tid]  = b_ih[H + jg]     + b_hh[H + jg];
            sparam[320 + tid]  = b_ih[2 * H + jg];
            sparam[384 + tid]  = b_hh[2 * H + jg];
        }

        // stage all weights once (bf16 hi/lo, SW128)
        for (int c = 0; c < 4; c++) {
            for (int f = tid; f < 192 * 8; f += 512) {
                int rr = f >> 3, cc = f & 7;
                int g = rr >> 6, jj = rr & 63;
                size_t src = ((size_t)(g * H + j0 + jj)) * H + c * 64 + cc * 8;
                u32 d = sb + SM_W + c * 24576 + rr * 128 + ((cc * 16) ^ ((rr & 7) << 4));
                cp16(d, g_whi + src);
                cp16(d + SM_WLO_O, g_wlo + src);
            }
        }

        const int a_row  = lane & 15;
        const int a_colh = (lane >> 4) * 16;
        const int b_row  = ((lane >> 4) << 3) + (lane & 7);
        const int b_colh = ((lane >> 3) & 1) * 16;
        const int l4 = lane >> 2;
        const int lp = lane & 3;

        float2 hst[2][2];
        #pragma unroll
        for (int e = 0; e < 2; e++)
            #pragma unroll
            for (int sub = 0; sub < 2; sub++) {
                int rowg = b0 + wm * 16 + l4 + 8 * e;
                int jl = wn * 16 + 8 * sub + 2 * lp;
                hst[e][sub] = *(const float2*)&h0[(size_t)rowg * H + j0 + jl];
            }

        // pre-stage own chunk of h0 into buf0
        #pragma unroll
        for (int i = 0; i < 4; i++) {
            int f = tid + i * 512;
            int row = f >> 5, kp = f & 31;
            float2 hv = *(const float2*)&h0[(size_t)(b0 + row) * H + jc * 64 + 2 * kp];
            __nv_bfloat162 h2 = __floats2bfloat162_rn(hv.x, hv.y);
            __nv_bfloat162 l2 = __floats2bfloat162_rn(hv.x - __bfloat162float(h2.x),
                                                      hv.y - __bfloat162float(h2.y));
            u32 off = (u32)(row * 128) + (u32)((kp * 4) ^ ((row & 7) << 4));
            *(u32*)(smem + SM_A + off)        = bf2u(h2);
            *(u32*)(smem + SM_A + 8192 + off) = bf2u(l2);
        }
        cp_wait_all();
        __syncthreads();

        const u32 ab0 = sb + SM_A;
        const u32 ab1 = sb + SM_A + 16384;
        const int crow = tid >> 3;
        const int cgrp = tid & 7;
        const u32 coff = (u32)(crow * 128) + (u32)((cgrp * 16) ^ ((crow & 7) << 4));

        for (int t = 0; t < T; t++) {
            float xv0 = x[(size_t)t * B + b0 + wm * 16 + l4];
            float xv1 = x[(size_t)t * B + b0 + wm * 16 + l4 + 8];

            AccT A;
            #pragma unroll
            for (int g = 0; g < 3; g++)
                #pragma unroll
                for (int s = 0; s < 2; s++)
                    #pragma unroll
                    for (int q = 0; q < 4; q++) A.a[g][s][q] = 0.f;

            // own chunk first (no barrier needed)
            mma_section(A, ab0, sb + SM_W + jc * 24576, wm, wn, a_row, a_colh, b_row, b_colh);

            // wait for siblings' h_{t-1}: monotonic counter >= 4*t
            if (t > 0 && tid == 0) {
                u32 g;
                do {
                    asm volatile("ld.acquire.gpu.global.u32 %0, [%1];"
                                 : "=r"(g) : "l"(&g_cnt[bg * 32]));
                } while ((int)(g - (u32)(4 * t)) < 0);
            }
            __syncthreads();

            if (t == 0) {
                #pragma unroll
                for (int i = 1; i <= 3; i++) {
                    int c = (jc + i) & 3;
                    char* base = smem + SM_A + ((i & 1) ? 16384 : 0);
                    #pragma unroll
                    for (int k = 0; k < 4; k++) {
                        int f = tid + k * 512;
                        int row = f >> 5, kp = f & 31;
                        float2 hv = *(const float2*)&h0[(size_t)(b0 + row) * H + c * 64 + 2 * kp];
                        __nv_bfloat162 h2 = __floats2bfloat162_rn(hv.x, hv.y);
                        __nv_bfloat162 l2 = __floats2bfloat162_rn(hv.x - __bfloat162float(h2.x),
                                                                  hv.y - __bfloat162float(h2.y));
                        u32 off = (u32)(row * 128) + (u32)((kp * 4) ^ ((row & 7) << 4));
                        *(u32*)(base + off)        = bf2u(h2);
                        *(u32*)(base + 8192 + off) = bf2u(l2);
                    }
                    __syncthreads();
                    mma_section(A, (i & 1) ? ab1 : ab0, sb + SM_W + c * 24576,
                                wm, wn, a_row, a_colh, b_row, b_colh);
                    if (i < 3) __syncthreads();
                }
            } else {
                int c1 = (jc + 1) & 3, c2 = (jc + 2) & 3, c3 = (jc + 3) & 3;
                size_t prev = (size_t)(t - 1) * B + b0 + crow;
                cp16(ab1 + coff,        &g_hhi[prev * 128 + c1 * 32 + cgrp * 4]);
                cp16(ab1 + 8192 + coff, &g_hlo[prev * 128 + c1 * 32 + cgrp * 4]);
                cp_commit();
                cp16(ab0 + coff,        &g_hhi[prev * 128 + c2 * 32 + cgrp * 4]);
                cp16(ab0 + 8192 + coff, &g_hlo[prev * 128 + c2 * 32 + cgrp * 4]);
                cp_commit();
                cp_wait_group<1>();
                __syncthreads();
                mma_section(A, ab1, sb + SM_W + c1 * 24576, wm, wn, a_row, a_colh, b_row, b_colh);
                cp_wait_group<0>();
                __syncthreads();
                cp16(ab1 + coff,        &g_hhi[prev * 128 + c3 * 32 + cgrp * 4]);
                cp16(ab1 + 8192 + coff, &g_hlo[prev * 128 + c3 * 32 + cgrp * 4]);
                cp_commit();
                mma_section(A, ab0, sb + SM_W + c2 * 24576, wm, wn, a_row, a_colh, b_row, b_colh);
                cp_wait_group<0>();
                __syncthreads();
                mma_section(A, ab1, sb + SM_W + c3 * 24576, wm, wn, a_row, a_colh, b_row, b_colh);
            }

            // epilogue: gates; update regs; write bf16 hi/lo (t-indexed) + buf0
            #pragma unroll
            for (int e = 0; e < 2; e++) {
                int rowl = wm * 16 + l4 + 8 * e;
                int rowg = b0 + rowl;
                float xv = e ? xv1 : xv0;
                #pragma unroll
                for (int sub = 0; sub < 2; sub++) {
                    int jl = wn * 16 + 8 * sub + 2 * lp;
                    float hn0, hn1;
                    {
                        int j = jl;
                        float r = fast_sigmoid(xv * sparam[j] + sparam[192 + j]
                                               + A.a[0][sub][e * 2]);
                        float z = fast_sigmoid(xv * sparam[64 + j] + sparam[256 + j]
                                               + A.a[1][sub][e * 2]);
                        float n = fast_tanh(xv * sparam[128 + j] + sparam[320 + j]
                                            + r * (A.a[2][sub][e * 2] + sparam[384 + j]));
                        hn0 = (1.f - z) * n + z * hst[e][sub].x;
                    }
                    {
                        int j = jl + 1;
                        float r = fast_sigmoid(xv * sparam[j] + sparam[192 + j]
                                               + A.a[0][sub][e * 2 + 1]);
                        float z = fast_sigmoid(xv * sparam[64 + j] + sparam[256 + j]
                                               + A.a[1][sub][e * 2 + 1]);
                        float n = fast_tanh(xv * sparam[128 + j] + sparam[320 + j]
                                            + r * (A.a[2][sub][e * 2 + 1] + sparam[384 + j]));
                        hn1 = (1.f - z) * n + z * hst[e][sub].y;
                    }
                    hst[e][sub] = make_float2(hn0, hn1);

                    __nv_bfloat162 h2 = __floats2bfloat162_rn(hn0, hn1);
                    __nv_bfloat162 l2 = __floats2bfloat162_rn(hn0 - __bfloat162float(h2.x),
                                                              hn1 - __bfloat162float(h2.y));
                    int kp = wn * 8 + 4 * sub + lp;
                    size_t gi = ((size_t)t * B + rowg) * 128 + jc * 32 + kp;
                    g_hhi[gi] = bf2u(h2);
                    g_hlo[gi] = bf2u(l2);
                    u32 off = (u32)(rowl * 128) + (u32)((kp * 4) ^ ((rowl & 7) << 4));
                    *(u32*)(smem + SM_A + off)        = bf2u(h2);
                    *(u32*)(smem + SM_A + 8192 + off) = bf2u(l2);
                }
            }

            // release h_t: single monotonic atomicAdd (no post-sync needed)
            __threadfence();
            __syncthreads();
            if (tid == 0) atomicAdd(&g_cnt[bg * 32], 1u);
        }
        __syncthreads();
    }

    // =====================================================================
    // MLP consumer part (all blocks; queue-driven, gated on g_cnt)
    // =====================================================================
    {
        float* sm  = (float*)smem;
        float* xt  = sm;            // [64][256]
        float* w1s = sm + 16384;    // [64][260]
        float* h1s = sm + 33024;    // [64][64]
        float* h2t = sm + 37120;    // [64][66]
        float* w3s = sm;            // alias xt
        float* w2s = sm + 16384;    // alias w1s
        u32* qs = (u32*)(smem + SM_Q);

        const int jp = tid & 31;
        const int rg = (tid >> 5) & 7;
        const bool act = tid < 256;

        for (;;) {
            __syncthreads();
            if (tid == 0) *qs = atomicAdd(&g_q, 1u);
            __syncthreads();
            u32 q = *qs;
            if (q >= (u32)NTILE) break;
            int tt  = (int)(q >> 5);
            int bgq = (int)(q & 31);

            if (tid == 0) {
                u32 target = (u32)(4 * (tt + 1)), g;
                do {
                    asm volatile("ld.acquire.gpu.global.u32 %0, [%1];"
                                 : "=r"(g) : "l"(&g_cnt[bgq * 32]));
                } while ((int)(g - target) < 0);
            }
            __syncthreads();

            const size_t row0 = (size_t)q * RROWS;

            // reconstruct xt fp32 from bf16 hi/lo
            {
                const u32* hh = g_hhi + row0 * 128;
                const u32* ll = g_hlo + row0 * 128;
                for (int i = tid; i < RROWS * 128; i += 512) {
                    float2 a = u2f2(hh[i]);
                    float2 b = u2f2(ll[i]);
                    int row = i >> 7, kp = i & 127;
                    *(float2*)&xt[row * 256 + 2 * kp] = make_float2(a.x + b.x, a.y + b.y);
                }
            }
            for (int f = tid; f < H * H1; f += 512) {
                int jj = f & 63; int k = f >> 6;
                w1s[jj * 260 + k] = w1[f];
            }
            __syncthreads();

            // Stage 1
            if (act) {
                float acc[8][2];
                #pragma unroll
                for (int i = 0; i < 8; i++) { acc[i][0] = 0.f; acc[i][1] = 0.f; }
                #pragma unroll 4
                for (int k = 0; k < H; k += 4) {
                    float4 wa = *(const float4*)&w1s[(2 * jp) * 260 + k];
                    float4 wb = *(const float4*)&w1s[(2 * jp + 1) * 260 + k];
                    #pragma unroll
                    for (int i = 0; i < 8; i++) {
                        float4 xv = *(const float4*)&xt[(rg * 8 + i) * H + k];
                        acc[i][0] += xv.x * wa.x + xv.y * wa.y + xv.z * wa.z + xv.w * wa.w;
                        acc[i][1] += xv.x * wb.x + xv.y * wb.y + xv.z * wb.z + xv.w * wb.w;
                    }
                }
                float ba = b1[2 * jp], bb = b1[2 * jp + 1];
                #pragma unroll
                for (int i = 0; i < 8; i++) {
                    h1s[(rg * 8 + i) * 64 + 2 * jp]     = fast_elu(acc[i][0] + ba);
                    h1s[(rg * 8 + i) * 64 + 2 * jp + 1] = fast_elu(acc[i][1] + bb);
                }
            }
            __syncthreads();

            for (int f = tid; f < H1 * H2; f += 512) {
                int jj = f & 63; int k = f >> 6;
                w2s[jj * 68 + k] = w2[f];
            }
            __syncthreads();

            // Stage 2 (h2 transposed)
            if (act) {
                float acc[8][2];
                #pragma unroll
                for (int i = 0; i < 8; i++) { acc[i][0] = 0.f; acc[i][1] = 0.f; }
                #pragma unroll
                for (int k = 0; k < H1; k += 4) {
                    float4 wa = *(const float4*)&w2s[(2 * jp) * 68 + k];
                    float4 wb = *(const float4*)&w2s[(2 * jp + 1) * 68 + k];
                    #pragma unroll
                    for (int i = 0; i < 8; i++) {
                        float4 xv = *(const float4*)&h1s[(rg * 8 + i) * 64 + k];
                        acc[i][0] += xv.x * wa.x + xv.y * wa.y + xv.z * wa.z + xv.w * wa.w;
                        acc[i][1] += xv.x * wb.x + xv.y * wb.y + xv.z * wb.z + xv.w * wb.w;
                    }
                }
                float ba = b2[2 * jp], bb = b2[2 * jp + 1];
                #pragma unroll
                for (int i = 0; i < 8; i++) {
                    int row = rg * 8 + i;
                    h2t[(2 * jp) * 66 + row]     = fast_elu(acc[i][0] + ba);
                    h2t[(2 * jp + 1) * 66 + row] = fast_elu(acc[i][1] + bb);
                }
            }
            __syncthreads();

            // Stage 3: packed fp32x2 over row pairs
            for (int c0 = 0; c0 < OUTD; c0 += 128) {
                for (int f = tid; f < 64 * 128; f += 512) {
                    int c = f & 127; int k = f >> 7;
                    int cg = c0 + c;
                    w3s[k * 128 + c] = (cg < OUTD) ? w3[(size_t)k * OUTD + cg] : 0.f;
                }
                __syncthreads();

                if (act) {
                    u64 acc[4][4];
                    #pragma unroll
                    for (int rp = 0; rp < 4; rp++)
                        #pragma unroll
                        for (int qq = 0; qq < 4; qq++) acc[rp][qq] = 0ull;

                    #pragma unroll 4
                    for (int k = 0; k < H2; k++) {
                        u64 wd[4];
                        #pragma unroll
                        for (int qq = 0; qq < 4; qq++) {
                            float w = w3s[k * 128 + jp + 32 * qq];
                            wd[qq] = pack2(w, w);
                        }
                        const float* hp = &h2t[k * 66 + rg * 8];
                        u64 hv0 = *(const u64*)(hp + 0);
                        u64 hv1 = *(const u64*)(hp + 2);
                        u64 hv2 = *(const u64*)(hp + 4);
                        u64 hv3 = *(const u64*)(hp + 6);
                        #pragma unroll
                        for (int qq = 0; qq < 4; qq++) {
                            acc[0][qq] = ffma2(hv0, wd[qq], acc[0][qq]);
                            acc[1][qq] = ffma2(hv1, wd[qq], acc[1][qq]);
                            acc[2][qq] = ffma2(hv2, wd[qq], acc[2][qq]);
                            acc[3][qq] = ffma2(hv3, wd[qq], acc[3][qq]);
                        }
                    }

                    #pragma unroll
                    for (int qq = 0; qq < 4; qq++) {
                        int cg = c0 + jp + 32 * qq;
                        if (cg < OUTD) {
                            float bq = b3[cg];
                            #pragma unroll
                            for (int rp = 0; rp < 4; rp++) {
                                float2 v = unpack2(acc[rp][qq]);
                                size_t row = row0 + rg * 8 + 2 * rp;
                                out[row * OUTD + cg]       = v.x + bq;
                                out[(row + 1) * OUTD + cg] = v.y + bq;
                            }
                        }
                    }
                }
                __syncthreads();
            }
        }
    }
}

__global__ void copy_h_kernel(float* __restrict__ out)
{
    int i = blockIdx.x * blockDim.x + threadIdx.x;
    if (i < B * H / 2) {
        size_t base = (size_t)(T - 1) * B * 128;
        float2 a = u2f2(g_hhi[base + i]);
        float2 b = u2f2(g_hlo[base + i]);
        *(float2*)&out[2 * i] = make_float2(a.x + b.x, a.y + b.y);
    }
}

// ---------------------------------------------------------------------------
extern "C" void kernel_launch(void* const* d_in, const int* in_sizes, int n_in,
                              void* d_out, int out_size)
{
    const float* x    = (const float*)d_in[0];
    const float* h0   = (const float*)d_in[1];
    const float* w_ih = (const float*)d_in[2];
    const float* w_hh = (const float*)d_in[3];
    const float* b_ih = (const float*)d_in[4];
    const float* b_hh = (const float*)d_in[5];
    const float* w1   = (const float*)d_in[6];
    const float* b1   = (const float*)d_in[7];
    const float* w2   = (const float*)d_in[8];
    const float* b2   = (const float*)d_in[9];
    const float* w3   = (const float*)d_in[10];
    const float* b3   = (const float*)d_in[11];
    float* out = (float*)d_out;

    cudaFuncSetAttribute(fused_persist,
                         cudaFuncAttributeMaxDynamicSharedMemorySize, FUSED_SMEM);

    prep_w_kernel<<<(3 * H * H + 255) / 256, 256>>>(w_hh);

    fused_persist<<<GRID_P, 512, FUSED_SMEM>>>(h0, x, w_ih, b_ih, b_hh,
                                               w1, b1, w2, b2, w3, b3, out);

    copy_h_kernel<<<(B * H / 2 + 255) / 256, 256>>>(out + (size_t)T * B * OUTD);
}